// round 4
// baseline (speedup 1.0000x reference)
#include <cuda_runtime.h>
#include <cuda_bf16.h>
#include <cstdint>

#define NROWS 8192
#define DCOLS 512

// ---------------- scratch (device globals: allocation-free) ----------------
__device__ __align__(256) __nv_bfloat16 g_Ahi[(size_t)NROWS * NROWS];   // 128 MB
__device__ __align__(256) __nv_bfloat16 g_Alo[(size_t)NROWS * NROWS];   // 128 MB
__device__ __align__(256) __nv_bfloat16 g_Bhi[(size_t)DCOLS * NROWS];   // 8 MB [n][k]
__device__ __align__(256) __nv_bfloat16 g_Blo[(size_t)DCOLS * NROWS];   // 8 MB
__device__ float g_deg[NROWS];

// ---------------- PTX helpers (compute_100-safe: no 'a' features) ----------
__device__ __forceinline__ uint32_t smem_u32(const void* p) {
    uint32_t a;
    asm("{ .reg .u64 t; cvta.to.shared.u64 t, %1; cvt.u32.u64 %0, t; }" : "=r"(a) : "l"(p));
    return a;
}
__device__ __forceinline__ void cp16(uint32_t dst, const void* src) {
    asm volatile("cp.async.cg.shared.global [%0], [%1], 16;" :: "r"(dst), "l"(src));
}
__device__ __forceinline__ void ldsm4(uint32_t* r, uint32_t addr) {
    asm volatile("ldmatrix.sync.aligned.m8n8.x4.shared.b16 {%0,%1,%2,%3}, [%4];"
                 : "=r"(r[0]), "=r"(r[1]), "=r"(r[2]), "=r"(r[3]) : "r"(addr));
}
__device__ __forceinline__ void mma_bf16(float* c, const uint32_t* a, const uint32_t* b) {
    asm("mma.sync.aligned.m16n8k16.row.col.f32.bf16.bf16.f32 "
        "{%0,%1,%2,%3}, {%4,%5,%6,%7}, {%8,%9}, {%0,%1,%2,%3};"
        : "+f"(c[0]), "+f"(c[1]), "+f"(c[2]), "+f"(c[3])
        : "r"(a[0]), "r"(a[1]), "r"(a[2]), "r"(a[3]), "r"(b[0]), "r"(b[1]));
}

// ---------------- P1: row stats + A split + XLA-order deg ----------------
// hv = fl(1 / max(fl(sqrt(cnt)), 1e-12))  (RN ops, matching XLA lowering)
// a' = fl(inc + (inc>0)*hv); bf16 hi/lo planes written from a'.
// deg = XLA-GPU row-reduce mimic over a': 1024 virtual threads, float2
// vectorized (elem = 2*vt+v + 2048*i, i=0..3), per-vthread vec acc ->
// horizontal add -> shfl_down tree (16..1) per virtual warp -> 32 partials
// in smem -> warp-0 shfl_down tree. Emulated on 256 real threads with
// vt = tid + 256*jv so virtual lane == real lane (shuffle pairing exact).
__global__ void __launch_bounds__(256) prep_rows(const float* __restrict__ inc) {
    __shared__ float row[NROWS];          // 32 KB
    __shared__ int   red_c[8];
    __shared__ float wpart[32];
    __shared__ float s_hv;

    const int r = blockIdx.x;
    const int tid = threadIdx.x;
    const int lane = tid & 31, warp = tid >> 5;

    const float4* src = (const float4*)(inc + (size_t)r * NROWS);
    float4* dst = (float4*)row;
    int cnt = 0;
    for (int i = tid; i < NROWS / 4; i += 256) {
        float4 v = src[i];
        dst[i] = v;
        cnt += (v.x > 0.f) + (v.y > 0.f) + (v.z > 0.f) + (v.w > 0.f);
    }
    for (int o = 16; o; o >>= 1) cnt += __shfl_xor_sync(0xFFFFFFFFu, cnt, o);
    if (lane == 0) red_c[warp] = cnt;
    __syncthreads();
    if (tid == 0) {
        int c = 0;
        #pragma unroll
        for (int i = 0; i < 8; i++) c += red_c[i];
        float denom = __fsqrt_rn((float)c);
        denom = fmaxf(denom, 1e-12f);
        s_hv = __fdiv_rn(1.0f, denom);
    }
    __syncthreads();
    const float hv = s_hv;

    // ---- deg: exact XLA-GPU order mimic ----
    float accx[4], accy[4];
    #pragma unroll
    for (int jv = 0; jv < 4; jv++) { accx[jv] = 0.f; accy[jv] = 0.f; }
    #pragma unroll
    for (int jv = 0; jv < 4; jv++) {
        const int vt = tid + 256 * jv;
        #pragma unroll
        for (int i = 0; i < 4; i++) {
            const int j = 2 * vt + 2048 * i;
            float x = row[j];
            float y = row[j + 1];
            if (x > 0.f) x = x + hv;
            if (y > 0.f) y = y + hv;
            accx[jv] += x;
            accy[jv] += y;
        }
    }
    #pragma unroll
    for (int jv = 0; jv < 4; jv++) {
        float s = accx[jv] + accy[jv];
        s += __shfl_down_sync(0xFFFFFFFFu, s, 16);
        s += __shfl_down_sync(0xFFFFFFFFu, s, 8);
        s += __shfl_down_sync(0xFFFFFFFFu, s, 4);
        s += __shfl_down_sync(0xFFFFFFFFu, s, 2);
        s += __shfl_down_sync(0xFFFFFFFFu, s, 1);
        if (lane == 0) wpart[jv * 8 + warp] = s;
    }
    __syncthreads();
    if (tid < 32) {
        float v = wpart[tid];
        v += __shfl_down_sync(0xFFFFFFFFu, v, 16);
        v += __shfl_down_sync(0xFFFFFFFFu, v, 8);
        v += __shfl_down_sync(0xFFFFFFFFu, v, 4);
        v += __shfl_down_sync(0xFFFFFFFFu, v, 2);
        v += __shfl_down_sync(0xFFFFFFFFu, v, 1);
        if (tid == 0) g_deg[r] = v;
    }

    // ---- bf16 hi/lo planes from a' ----
    __nv_bfloat162* hi = (__nv_bfloat162*)(g_Ahi + (size_t)r * NROWS);
    __nv_bfloat162* lo = (__nv_bfloat162*)(g_Alo + (size_t)r * NROWS);
    for (int i = tid; i < NROWS / 2; i += 256) {
        float a = row[2 * i], b = row[2 * i + 1];
        if (a > 0.f) a = a + hv;
        if (b > 0.f) b = b + hv;
        __nv_bfloat16 ah = __float2bfloat16(a);
        __nv_bfloat16 bh = __float2bfloat16(b);
        float al = a - __bfloat162float(ah);
        float bl = b - __bfloat162float(bh);
        hi[i] = __halves2bfloat162(ah, bh);
        lo[i] = __halves2bfloat162(__float2bfloat16(al), __float2bfloat16(bl));
    }
}

// ---------------- P2: cur [k][n] -> B planes [n][k] (transpose + split) ------
__global__ void __launch_bounds__(256) prep_B(const float* __restrict__ cur) {
    __shared__ float t[32][33];
    const int k0 = blockIdx.x * 32;
    const int n0 = blockIdx.y * 32;
    const int tx = threadIdx.x, ty = threadIdx.y;
    for (int i = ty; i < 32; i += 8)
        t[i][tx] = cur[(size_t)(k0 + i) * DCOLS + n0 + tx];
    __syncthreads();
    for (int i = ty; i < 32; i += 8) {
        float v = t[tx][i];                  // cur[k0+tx][n0+i]
        size_t o = (size_t)(n0 + i) * NROWS + (size_t)(k0 + tx);
        __nv_bfloat16 h = __float2bfloat16(v);
        g_Bhi[o] = h;
        g_Blo[o] = __float2bfloat16(v - __bfloat162float(h));
    }
}

// ---------------- P3: mma.sync bf16x3 GEMM, 128x256 tile, one wave ----------
constexpr int BM = 128, BN = 256, BK = 32, STAGES = 4;
constexpr int NCH = NROWS / BK;                 // 256 k-chunks
constexpr int A_BYTES = BM * 128;               // 16 KB  (row: hi 64B | lo 64B)
constexpr int B_BYTES = BN * 128;               // 32 KB
constexpr int STAGE_BYTES = A_BYTES + B_BYTES;  // 48 KB
constexpr int SMEM_TOTAL = 1024 + STAGES * STAGE_BYTES;  // 197632

__device__ __forceinline__ void load_stage(uint32_t st, int c, int m0, int n0, int tid) {
    const size_t rs = (size_t)NROWS * 2;     // 16384 B row stride
    const size_t kb = (size_t)c * 64;        // 32 bf16 = 64 B along k
    const char* Ah = (const char*)g_Ahi + (size_t)m0 * rs + kb;
    const char* Al = (const char*)g_Alo + (size_t)m0 * rs + kb;
    const char* Bh = (const char*)g_Bhi + (size_t)n0 * rs + kb;
    const char* Bl = (const char*)g_Blo + (size_t)n0 * rs + kb;
    #pragma unroll
    for (int i = 0; i < 2; i++) {            // A: 1024 granules
        int idx = i * 512 + tid, row = idx >> 3, ch = idx & 7;
        const char* s = (ch < 4 ? Ah : Al) + (size_t)row * rs + (size_t)(ch & 3) * 16;
        cp16(st + row * 128 + ((ch ^ (row & 7)) << 4), s);
    }
    const uint32_t bs = st + A_BYTES;
    #pragma unroll
    for (int i = 0; i < 4; i++) {            // B: 2048 granules
        int idx = i * 512 + tid, row = idx >> 3, ch = idx & 7;
        const char* s = (ch < 4 ? Bh : Bl) + (size_t)row * rs + (size_t)(ch & 3) * 16;
        cp16(bs + row * 128 + ((ch ^ (row & 7)) << 4), s);
    }
}

__global__ void __launch_bounds__(512, 1) gemm_kernel(float* __restrict__ out) {
    extern __shared__ char smem_raw[];
    const uint32_t sb = (smem_u32(smem_raw) + 1023u) & ~1023u;
    const int tid = threadIdx.x, lane = tid & 31, w = tid >> 5;
    const int wm = w & 3, wn = w >> 2;       // 4 x 4 warp grid, warp tile 32x64
    const int m0 = blockIdx.y * BM, n0 = blockIdx.x * BN;

    // preload 3 stages
    #pragma unroll
    for (int s = 0; s < 3; s++) {
        load_stage(sb + s * STAGE_BYTES, s, m0, n0, tid);
        asm volatile("cp.async.commit_group;" ::: "memory");
    }

    float acc[2][8][4] = {};                 // 64 regs

    // ldmatrix per-lane row constants
    int aRow[2], bRow[4];
    #pragma unroll
    for (int mi = 0; mi < 2; mi++) aRow[mi] = wm * 32 + mi * 16 + (lane & 15);
    #pragma unroll
    for (int f = 0; f < 4; f++)
        bRow[f] = wn * 64 + f * 16 + ((lane >> 4) << 3) + (lane & 7);
    const int aSel = lane >> 4;              // k8 selector for A
    const int bSel = (lane >> 3) & 1;        // k8 selector for B

    for (int c = 0; c < NCH; c++) {
        asm volatile("cp.async.wait_group 2;" ::: "memory");
        __syncthreads();
        if (c + 3 < NCH) load_stage(sb + ((c + 3) & 3) * STAGE_BYTES, c + 3, m0, n0, tid);
        asm volatile("cp.async.commit_group;" ::: "memory");  // may be empty (tail)

        const uint32_t st = sb + (c & 3) * STAGE_BYTES;
        const uint32_t aB = st, bB = st + A_BYTES;

        #pragma unroll
        for (int q = 0; q < 2; q++) {        // two k16 halves of the chunk
            uint32_t bh[16], ah[8], al[8];
            #pragma unroll
            for (int f = 0; f < 4; f++)      // Bhi (chunks 0-3)
                ldsm4(&bh[4 * f], bB + bRow[f] * 128 +
                      (((q * 2 + bSel) ^ (bRow[f] & 7)) << 4));
            #pragma unroll
            for (int mi = 0; mi < 2; mi++)   // Ahi
                ldsm4(&ah[4 * mi], aB + aRow[mi] * 128 +
                      (((q * 2 + aSel) ^ (aRow[mi] & 7)) << 4));
            #pragma unroll
            for (int mi = 0; mi < 2; mi++)
                #pragma unroll
                for (int ni = 0; ni < 8; ni++)
                    mma_bf16(acc[mi][ni], &ah[4 * mi], &bh[2 * ni]);   // hi*hi
            #pragma unroll
            for (int mi = 0; mi < 2; mi++)   // Alo (chunks 4-7)
                ldsm4(&al[4 * mi], aB + aRow[mi] * 128 +
                      (((4 + q * 2 + aSel) ^ (aRow[mi] & 7)) << 4));
            #pragma unroll
            for (int mi = 0; mi < 2; mi++)
                #pragma unroll
                for (int ni = 0; ni < 8; ni++)
                    mma_bf16(acc[mi][ni], &al[4 * mi], &bh[2 * ni]);   // lo*hi
            #pragma unroll
            for (int f = 0; f < 4; f++)      // Blo overwrites bh
                ldsm4(&bh[4 * f], bB + bRow[f] * 128 +
                      (((4 + q * 2 + bSel) ^ (bRow[f] & 7)) << 4));
            #pragma unroll
            for (int mi = 0; mi < 2; mi++)
                #pragma unroll
                for (int ni = 0; ni < 8; ni++)
                    mma_bf16(acc[mi][ni], &ah[4 * mi], &bh[2 * ni]);   // hi*lo
        }
    }

    // epilogue: out[m][n] = fea / deg   (RN division, matching reference)
    const int cw = n0 + wn * 64 + (lane & 3) * 2;
    #pragma unroll
    for (int mi = 0; mi < 2; mi++) {
        const int r0 = m0 + wm * 32 + mi * 16 + (lane >> 2);
        const float d0 = g_deg[r0];
        const float d1 = g_deg[r0 + 8];
        float* p0 = out + (size_t)r0 * DCOLS;
        float* p1 = out + (size_t)(r0 + 8) * DCOLS;
        #pragma unroll
        for (int ni = 0; ni < 8; ni++) {
            float2 v0 = make_float2(__fdiv_rn(acc[mi][ni][0], d0),
                                    __fdiv_rn(acc[mi][ni][1], d0));
            float2 v1 = make_float2(__fdiv_rn(acc[mi][ni][2], d1),
                                    __fdiv_rn(acc[mi][ni][3], d1));
            *(float2*)(p0 + cw + ni * 8) = v0;
            *(float2*)(p1 + cw + ni * 8) = v1;
        }
    }
}

// ---------------- launch ----------------
extern "C" void kernel_launch(void* const* d_in, const int* in_sizes, int n_in,
                              void* d_out, int out_size) {
    const float* cur = (const float*)d_in[0];
    const float* inc = (const float*)d_in[1];
    if (n_in >= 2 && in_sizes[0] == NROWS * NROWS) {  // defensive input-order check
        inc = (const float*)d_in[0];
        cur = (const float*)d_in[1];
    }
    cudaFuncSetAttribute(gemm_kernel, cudaFuncAttributeMaxDynamicSharedMemorySize,
                         SMEM_TOTAL);

    prep_rows<<<NROWS, 256>>>(inc);
    prep_B<<<dim3(NROWS / 32, DCOLS / 32), dim3(32, 8)>>>(cur);
    gemm_kernel<<<dim3(DCOLS / BN, NROWS / BM), 512, SMEM_TOTAL>>>((float*)d_out);
}

// round 5
// speedup vs baseline: 1.0242x; 1.0242x over previous
#include <cuda_runtime.h>
#include <cuda_bf16.h>
#include <cstdint>

#define NROWS 8192
#define DCOLS 512

// ---------------- scratch (device globals: allocation-free) ----------------
__device__ __align__(256) __nv_bfloat16 g_Ahi[(size_t)NROWS * NROWS];   // 128 MB
__device__ __align__(256) __nv_bfloat16 g_Alo[(size_t)NROWS * NROWS];   // 128 MB
__device__ __align__(256) __nv_bfloat16 g_Bhi[(size_t)DCOLS * NROWS];   // 8 MB [n][k]
__device__ __align__(256) __nv_bfloat16 g_Blo[(size_t)DCOLS * NROWS];   // 8 MB
__device__ float g_deg[NROWS];

// ---------------- PTX helpers (compute_100-safe: no 'a' features) ----------
__device__ __forceinline__ uint32_t smem_u32(const void* p) {
    uint32_t a;
    asm("{ .reg .u64 t; cvta.to.shared.u64 t, %1; cvt.u32.u64 %0, t; }" : "=r"(a) : "l"(p));
    return a;
}
__device__ __forceinline__ void cp16(uint32_t dst, const void* src) {
    asm volatile("cp.async.cg.shared.global [%0], [%1], 16;" :: "r"(dst), "l"(src));
}
__device__ __forceinline__ void ldsm4(uint32_t* r, uint32_t addr) {
    asm volatile("ldmatrix.sync.aligned.m8n8.x4.shared.b16 {%0,%1,%2,%3}, [%4];"
                 : "=r"(r[0]), "=r"(r[1]), "=r"(r[2]), "=r"(r[3]) : "r"(addr));
}
__device__ __forceinline__ void mma_bf16(float* c, const uint32_t* a, const uint32_t* b) {
    asm("mma.sync.aligned.m16n8k16.row.col.f32.bf16.bf16.f32 "
        "{%0,%1,%2,%3}, {%4,%5,%6,%7}, {%8,%9}, {%0,%1,%2,%3};"
        : "+f"(c[0]), "+f"(c[1]), "+f"(c[2]), "+f"(c[3])
        : "r"(a[0]), "r"(a[1]), "r"(a[2]), "r"(a[3]), "r"(b[0]), "r"(b[1]));
}

// ---------------- P1: row stats + A split + XLA-order deg ----------------
__global__ void __launch_bounds__(256) prep_rows(const float* __restrict__ inc) {
    __shared__ float row[NROWS];          // 32 KB
    __shared__ int   red_c[8];
    __shared__ float wpart[32];
    __shared__ float s_hv;

    const int r = blockIdx.x;
    const int tid = threadIdx.x;
    const int lane = tid & 31, warp = tid >> 5;

    const float4* src = (const float4*)(inc + (size_t)r * NROWS);
    float4* dst = (float4*)row;
    int cnt = 0;
    for (int i = tid; i < NROWS / 4; i += 256) {
        float4 v = src[i];
        dst[i] = v;
        cnt += (v.x > 0.f) + (v.y > 0.f) + (v.z > 0.f) + (v.w > 0.f);
    }
    for (int o = 16; o; o >>= 1) cnt += __shfl_xor_sync(0xFFFFFFFFu, cnt, o);
    if (lane == 0) red_c[warp] = cnt;
    __syncthreads();
    if (tid == 0) {
        int c = 0;
        #pragma unroll
        for (int i = 0; i < 8; i++) c += red_c[i];
        float denom = __fsqrt_rn((float)c);
        denom = fmaxf(denom, 1e-12f);
        s_hv = __fdiv_rn(1.0f, denom);
    }
    __syncthreads();
    const float hv = s_hv;

    // deg: XLA-GPU row-reduce order mimic (1024 virtual threads on 256 real)
    float accx[4], accy[4];
    #pragma unroll
    for (int jv = 0; jv < 4; jv++) { accx[jv] = 0.f; accy[jv] = 0.f; }
    #pragma unroll
    for (int jv = 0; jv < 4; jv++) {
        const int vt = tid + 256 * jv;
        #pragma unroll
        for (int i = 0; i < 4; i++) {
            const int j = 2 * vt + 2048 * i;
            float x = row[j];
            float y = row[j + 1];
            if (x > 0.f) x = x + hv;
            if (y > 0.f) y = y + hv;
            accx[jv] += x;
            accy[jv] += y;
        }
    }
    #pragma unroll
    for (int jv = 0; jv < 4; jv++) {
        float s = accx[jv] + accy[jv];
        s += __shfl_down_sync(0xFFFFFFFFu, s, 16);
        s += __shfl_down_sync(0xFFFFFFFFu, s, 8);
        s += __shfl_down_sync(0xFFFFFFFFu, s, 4);
        s += __shfl_down_sync(0xFFFFFFFFu, s, 2);
        s += __shfl_down_sync(0xFFFFFFFFu, s, 1);
        if (lane == 0) wpart[jv * 8 + warp] = s;
    }
    __syncthreads();
    if (tid < 32) {
        float v = wpart[tid];
        v += __shfl_down_sync(0xFFFFFFFFu, v, 16);
        v += __shfl_down_sync(0xFFFFFFFFu, v, 8);
        v += __shfl_down_sync(0xFFFFFFFFu, v, 4);
        v += __shfl_down_sync(0xFFFFFFFFu, v, 2);
        v += __shfl_down_sync(0xFFFFFFFFu, v, 1);
        if (tid == 0) g_deg[r] = v;
    }

    // bf16 hi/lo planes from a'
    __nv_bfloat162* hi = (__nv_bfloat162*)(g_Ahi + (size_t)r * NROWS);
    __nv_bfloat162* lo = (__nv_bfloat162*)(g_Alo + (size_t)r * NROWS);
    for (int i = tid; i < NROWS / 2; i += 256) {
        float a = row[2 * i], b = row[2 * i + 1];
        if (a > 0.f) a = a + hv;
        if (b > 0.f) b = b + hv;
        __nv_bfloat16 ah = __float2bfloat16(a);
        __nv_bfloat16 bh = __float2bfloat16(b);
        float al = a - __bfloat162float(ah);
        float bl = b - __bfloat162float(bh);
        hi[i] = __halves2bfloat162(ah, bh);
        lo[i] = __halves2bfloat162(__float2bfloat16(al), __float2bfloat16(bl));
    }
}

// ---------------- P2: cur [k][n] -> B planes [n][k] (transpose + split) ------
__global__ void __launch_bounds__(256) prep_B(const float* __restrict__ cur) {
    __shared__ float t[32][33];
    const int k0 = blockIdx.x * 32;
    const int n0 = blockIdx.y * 32;
    const int tx = threadIdx.x, ty = threadIdx.y;
    for (int i = ty; i < 32; i += 8)
        t[i][tx] = cur[(size_t)(k0 + i) * DCOLS + n0 + tx];
    __syncthreads();
    for (int i = ty; i < 32; i += 8) {
        float v = t[tx][i];                  // cur[k0+tx][n0+i]
        size_t o = (size_t)(n0 + i) * NROWS + (size_t)(k0 + tx);
        __nv_bfloat16 h = __float2bfloat16(v);
        g_Bhi[o] = h;
        g_Blo[o] = __float2bfloat16(v - __bfloat162float(h));
    }
}

// ---------------- P3: mma.sync bf16x3 GEMM, 128x256 tile, one wave ----------
constexpr int BM = 128, BN = 256, BK = 32, STAGES = 4;
constexpr int NCH = NROWS / BK;                 // 256 k-chunks
constexpr int A_BYTES = BM * 128;               // 16 KB  (row: hi 64B | lo 64B)
constexpr int B_BYTES = BN * 128;               // 32 KB
constexpr int STAGE_BYTES = A_BYTES + B_BYTES;  // 48 KB
constexpr int SMEM_TOTAL = 1024 + STAGES * STAGE_BYTES;  // 197632

__device__ __forceinline__ void load_stage(uint32_t st, int c, int m0, int n0, int tid) {
    const size_t rs = (size_t)NROWS * 2;     // 16384 B row stride
    const size_t kb = (size_t)c * 64;        // 32 bf16 = 64 B along k
    const char* Ah = (const char*)g_Ahi + (size_t)m0 * rs + kb;
    const char* Al = (const char*)g_Alo + (size_t)m0 * rs + kb;
    const char* Bh = (const char*)g_Bhi + (size_t)n0 * rs + kb;
    const char* Bl = (const char*)g_Blo + (size_t)n0 * rs + kb;
    #pragma unroll
    for (int i = 0; i < 2; i++) {            // A: 1024 granules
        int idx = i * 512 + tid, row = idx >> 3, ch = idx & 7;
        const char* s = (ch < 4 ? Ah : Al) + (size_t)row * rs + (size_t)(ch & 3) * 16;
        cp16(st + row * 128 + ((ch ^ (row & 7)) << 4), s);
    }
    const uint32_t bs = st + A_BYTES;
    #pragma unroll
    for (int i = 0; i < 4; i++) {            // B: 2048 granules
        int idx = i * 512 + tid, row = idx >> 3, ch = idx & 7;
        const char* s = (ch < 4 ? Bh : Bl) + (size_t)row * rs + (size_t)(ch & 3) * 16;
        cp16(bs + row * 128 + ((ch ^ (row & 7)) << 4), s);
    }
}

__global__ void __launch_bounds__(512, 1) gemm_kernel(float* __restrict__ out) {
    extern __shared__ char smem_raw[];
    const uint32_t sb = (smem_u32(smem_raw) + 1023u) & ~1023u;
    const int tid = threadIdx.x, lane = tid & 31, w = tid >> 5;
    const int wm = w & 3, wn = w >> 2;       // 4 x 4 warp grid, warp tile 32x64
    const int m0 = blockIdx.y * BM, n0 = blockIdx.x * BN;

    // preload 3 stages
    #pragma unroll
    for (int s = 0; s < 3; s++) {
        load_stage(sb + s * STAGE_BYTES, s, m0, n0, tid);
        asm volatile("cp.async.commit_group;" ::: "memory");
    }

    float acc[2][8][4] = {};                 // 64 regs

    // ldmatrix per-lane address constants
    int aRow[2], bRow[4];
    #pragma unroll
    for (int mi = 0; mi < 2; mi++) aRow[mi] = wm * 32 + mi * 16 + (lane & 15);
    #pragma unroll
    for (int f = 0; f < 4; f++)
        bRow[f] = wn * 64 + f * 16 + ((lane >> 4) << 3) + (lane & 7);
    const int aSel = lane >> 4;              // k8 selector for A
    const int bSel = (lane >> 3) & 1;        // k8 selector for B

    for (int c = 0; c < NCH; c++) {
        asm volatile("cp.async.wait_group 2;" ::: "memory");
        __syncthreads();
        if (c + 3 < NCH) load_stage(sb + ((c + 3) & 3) * STAGE_BYTES, c + 3, m0, n0, tid);
        asm volatile("cp.async.commit_group;" ::: "memory");  // may be empty (tail)

        const uint32_t st = sb + (c & 3) * STAGE_BYTES;
        const uint32_t aB = st, bB = st + A_BYTES;

        #pragma unroll
        for (int q = 0; q < 2; q++) {        // two k16 halves of the chunk
            uint32_t ah[8], al[8], bb[8];
            // A hi (k-chunks q*2+aSel) and A lo (4 + q*2+aSel)
            #pragma unroll
            for (int mi = 0; mi < 2; mi++) {
                ldsm4(&ah[4 * mi], aB + aRow[mi] * 128 +
                      (((q * 2 + aSel) ^ (aRow[mi] & 7)) << 4));
                ldsm4(&al[4 * mi], aB + aRow[mi] * 128 +
                      (((4 + q * 2 + aSel) ^ (aRow[mi] & 7)) << 4));
            }
            // stream B in two 32-column halves through an 8-reg buffer
            #pragma unroll
            for (int h = 0; h < 2; h++) {
                // Bhi half h (fragments f = 2h, 2h+1 -> ni = 4h..4h+3)
                #pragma unroll
                for (int g = 0; g < 2; g++) {
                    const int f = 2 * h + g;
                    ldsm4(&bb[4 * g], bB + bRow[f] * 128 +
                          (((q * 2 + bSel) ^ (bRow[f] & 7)) << 4));
                }
                #pragma unroll
                for (int mi = 0; mi < 2; mi++)
                    #pragma unroll
                    for (int j = 0; j < 4; j++)
                        mma_bf16(acc[mi][4 * h + j], &ah[4 * mi], &bb[2 * j]);  // hi*hi
                #pragma unroll
                for (int mi = 0; mi < 2; mi++)
                    #pragma unroll
                    for (int j = 0; j < 4; j++)
                        mma_bf16(acc[mi][4 * h + j], &al[4 * mi], &bb[2 * j]);  // lo*hi
                // Blo half h overwrites the buffer
                #pragma unroll
                for (int g = 0; g < 2; g++) {
                    const int f = 2 * h + g;
                    ldsm4(&bb[4 * g], bB + bRow[f] * 128 +
                          (((4 + q * 2 + bSel) ^ (bRow[f] & 7)) << 4));
                }
                #pragma unroll
                for (int mi = 0; mi < 2; mi++)
                    #pragma unroll
                    for (int j = 0; j < 4; j++)
                        mma_bf16(acc[mi][4 * h + j], &ah[4 * mi], &bb[2 * j]);  // hi*lo
            }
        }
    }

    // epilogue: out[m][n] = fea / deg   (RN division, matching reference)
    const int cw = n0 + wn * 64 + (lane & 3) * 2;
    #pragma unroll
    for (int mi = 0; mi < 2; mi++) {
        const int r0 = m0 + wm * 32 + mi * 16 + (lane >> 2);
        const float d0 = g_deg[r0];
        const float d1 = g_deg[r0 + 8];
        float* p0 = out + (size_t)r0 * DCOLS;
        float* p1 = out + (size_t)(r0 + 8) * DCOLS;
        #pragma unroll
        for (int ni = 0; ni < 8; ni++) {
            float2 v0 = make_float2(__fdiv_rn(acc[mi][ni][0], d0),
                                    __fdiv_rn(acc[mi][ni][1], d0));
            float2 v1 = make_float2(__fdiv_rn(acc[mi][ni][2], d1),
                                    __fdiv_rn(acc[mi][ni][3], d1));
            *(float2*)(p0 + cw + ni * 8) = v0;
            *(float2*)(p1 + cw + ni * 8) = v1;
        }
    }
}

// ---------------- launch ----------------
extern "C" void kernel_launch(void* const* d_in, const int* in_sizes, int n_in,
                              void* d_out, int out_size) {
    const float* cur = (const float*)d_in[0];
    const float* inc = (const float*)d_in[1];
    if (n_in >= 2 && in_sizes[0] == NROWS * NROWS) {  // defensive input-order check
        inc = (const float*)d_in[0];
        cur = (const float*)d_in[1];
    }
    cudaFuncSetAttribute(gemm_kernel, cudaFuncAttributeMaxDynamicSharedMemorySize,
                         SMEM_TOTAL);

    prep_rows<<<NROWS, 256>>>(inc);
    prep_B<<<dim3(NROWS / 32, DCOLS / 32), dim3(32, 8)>>>(cur);
    gemm_kernel<<<dim3(DCOLS / BN, NROWS / BM), 512, SMEM_TOTAL>>>((float*)d_out);
}

// round 6
// speedup vs baseline: 1.0617x; 1.0366x over previous
#include <cuda_runtime.h>
#include <cuda_bf16.h>
#include <cstdint>

#define NROWS 8192
#define DCOLS 512

// ---------------- scratch (device globals: allocation-free) ----------------
__device__ __align__(256) __nv_bfloat16 g_Ahi[(size_t)NROWS * NROWS];   // 128 MB
__device__ __align__(256) __nv_bfloat16 g_Alo[(size_t)NROWS * NROWS];   // 128 MB
__device__ __align__(256) __nv_bfloat16 g_Bhi[(size_t)DCOLS * NROWS];   // 8 MB [n][k]
__device__ __align__(256) __nv_bfloat16 g_Blo[(size_t)DCOLS * NROWS];   // 8 MB
__device__ float g_deg[NROWS];

// ---------------- PTX helpers (compute_100-safe: no 'a' features) ----------
__device__ __forceinline__ uint32_t smem_u32(const void* p) {
    uint32_t a;
    asm("{ .reg .u64 t; cvta.to.shared.u64 t, %1; cvt.u32.u64 %0, t; }" : "=r"(a) : "l"(p));
    return a;
}
__device__ __forceinline__ void cp16(uint32_t dst, const void* src) {
    asm volatile("cp.async.cg.shared.global [%0], [%1], 16;" :: "r"(dst), "l"(src));
}
__device__ __forceinline__ void ldsm4(uint32_t* r, uint32_t addr) {
    asm volatile("ldmatrix.sync.aligned.m8n8.x4.shared.b16 {%0,%1,%2,%3}, [%4];"
                 : "=r"(r[0]), "=r"(r[1]), "=r"(r[2]), "=r"(r[3]) : "r"(addr));
}
__device__ __forceinline__ void mma_bf16(float* c, const uint32_t* a, const uint32_t* b) {
    asm("mma.sync.aligned.m16n8k16.row.col.f32.bf16.bf16.f32 "
        "{%0,%1,%2,%3}, {%4,%5,%6,%7}, {%8,%9}, {%0,%1,%2,%3};"
        : "+f"(c[0]), "+f"(c[1]), "+f"(c[2]), "+f"(c[3])
        : "r"(a[0]), "r"(a[1]), "r"(a[2]), "r"(a[3]), "r"(b[0]), "r"(b[1]));
}
__device__ __forceinline__ uint32_t pack_bf16(float a, float b) {
    __nv_bfloat162 h = __halves2bfloat162(__float2bfloat16(a), __float2bfloat16(b));
    return *(uint32_t*)&h;
}

// ---------------- P1: row stats + A split + XLA-order deg ----------------
__global__ void __launch_bounds__(256) prep_rows(const float* __restrict__ inc) {
    __shared__ float row[NROWS];          // 32 KB
    __shared__ int   red_c[8];
    __shared__ float wpart[32];
    __shared__ float s_hv;

    const int r = blockIdx.x;
    const int tid = threadIdx.x;
    const int lane = tid & 31, warp = tid >> 5;

    const float4* src = (const float4*)(inc + (size_t)r * NROWS);
    float4* dst = (float4*)row;
    int cnt = 0;
    for (int i = tid; i < NROWS / 4; i += 256) {
        float4 v = src[i];
        dst[i] = v;
        cnt += (v.x > 0.f) + (v.y > 0.f) + (v.z > 0.f) + (v.w > 0.f);
    }
    for (int o = 16; o; o >>= 1) cnt += __shfl_xor_sync(0xFFFFFFFFu, cnt, o);
    if (lane == 0) red_c[warp] = cnt;
    __syncthreads();
    if (tid == 0) {
        int c = 0;
        #pragma unroll
        for (int i = 0; i < 8; i++) c += red_c[i];
        float denom = __fsqrt_rn((float)c);
        denom = fmaxf(denom, 1e-12f);
        s_hv = __fdiv_rn(1.0f, denom);
    }
    __syncthreads();
    const float hv = s_hv;

    // deg: XLA-GPU row-reduce order mimic (1024 virtual threads on 256 real)
    float accx[4], accy[4];
    #pragma unroll
    for (int jv = 0; jv < 4; jv++) { accx[jv] = 0.f; accy[jv] = 0.f; }
    #pragma unroll
    for (int jv = 0; jv < 4; jv++) {
        const int vt = tid + 256 * jv;
        #pragma unroll
        for (int i = 0; i < 4; i++) {
            const int j = 2 * vt + 2048 * i;
            float x = row[j];
            float y = row[j + 1];
            if (x > 0.f) x = x + hv;
            if (y > 0.f) y = y + hv;
            accx[jv] += x;
            accy[jv] += y;
        }
    }
    #pragma unroll
    for (int jv = 0; jv < 4; jv++) {
        float s = accx[jv] + accy[jv];
        s += __shfl_down_sync(0xFFFFFFFFu, s, 16);
        s += __shfl_down_sync(0xFFFFFFFFu, s, 8);
        s += __shfl_down_sync(0xFFFFFFFFu, s, 4);
        s += __shfl_down_sync(0xFFFFFFFFu, s, 2);
        s += __shfl_down_sync(0xFFFFFFFFu, s, 1);
        if (lane == 0) wpart[jv * 8 + warp] = s;
    }
    __syncthreads();
    if (tid < 32) {
        float v = wpart[tid];
        v += __shfl_down_sync(0xFFFFFFFFu, v, 16);
        v += __shfl_down_sync(0xFFFFFFFFu, v, 8);
        v += __shfl_down_sync(0xFFFFFFFFu, v, 4);
        v += __shfl_down_sync(0xFFFFFFFFu, v, 2);
        v += __shfl_down_sync(0xFFFFFFFFu, v, 1);
        if (tid == 0) g_deg[r] = v;
    }

    // bf16 hi/lo planes from a' (16-byte vectorized stores)
    uint4* hi = (uint4*)(g_Ahi + (size_t)r * NROWS);
    uint4* lo = (uint4*)(g_Alo + (size_t)r * NROWS);
    for (int i = tid; i < NROWS / 8; i += 256) {
        float a[8];
        #pragma unroll
        for (int e = 0; e < 8; e++) {
            float v = row[8 * i + e];
            if (v > 0.f) v = v + hv;
            a[e] = v;
        }
        uint4 h, l;
        h.x = pack_bf16(a[0], a[1]); h.y = pack_bf16(a[2], a[3]);
        h.z = pack_bf16(a[4], a[5]); h.w = pack_bf16(a[6], a[7]);
        float rl[8];
        #pragma unroll
        for (int e = 0; e < 8; e++) {
            __nv_bfloat16 hb = __float2bfloat16(a[e]);
            rl[e] = a[e] - __bfloat162float(hb);
        }
        l.x = pack_bf16(rl[0], rl[1]); l.y = pack_bf16(rl[2], rl[3]);
        l.z = pack_bf16(rl[4], rl[5]); l.w = pack_bf16(rl[6], rl[7]);
        hi[i] = h;
        lo[i] = l;
    }
}

// ---------------- P2: cur [k][n] -> B planes [n][k] (transpose + split) ------
__global__ void __launch_bounds__(256) prep_B(const float* __restrict__ cur) {
    __shared__ float t[32][33];
    const int k0 = blockIdx.x * 32;
    const int n0 = blockIdx.y * 32;
    const int tx = threadIdx.x, ty = threadIdx.y;
    for (int i = ty; i < 32; i += 8)
        t[i][tx] = cur[(size_t)(k0 + i) * DCOLS + n0 + tx];
    __syncthreads();
    for (int i = ty; i < 32; i += 8) {
        float v = t[tx][i];                  // cur[k0+tx][n0+i]
        size_t o = (size_t)(n0 + i) * NROWS + (size_t)(k0 + tx);
        __nv_bfloat16 h = __float2bfloat16(v);
        g_Bhi[o] = h;
        g_Blo[o] = __float2bfloat16(v - __bfloat162float(h));
    }
}

// ---------------- P3: mma.sync bf16x3 GEMM -----------------------------------
// CTA tile 128x256, 256 threads, warp grid 2(m) x 4(n), warp tile 64x64.
constexpr int BM = 128, BN = 256, BK = 32, STAGES = 4;
constexpr int NCH = NROWS / BK;                 // 256 k-chunks
constexpr int A_BYTES = BM * 128;               // 16 KB  (row: hi 64B | lo 64B)
constexpr int B_BYTES = BN * 128;               // 32 KB
constexpr int STAGE_BYTES = A_BYTES + B_BYTES;  // 48 KB
constexpr int SMEM_TOTAL = 1024 + STAGES * STAGE_BYTES;  // 197632

__device__ __forceinline__ void load_stage(uint32_t st, int c, int m0, int n0, int tid) {
    const size_t rs = (size_t)NROWS * 2;     // 16384 B row stride
    const size_t kb = (size_t)c * 64;        // 32 bf16 = 64 B along k
    const char* Ah = (const char*)g_Ahi + (size_t)m0 * rs + kb;
    const char* Al = (const char*)g_Alo + (size_t)m0 * rs + kb;
    const char* Bh = (const char*)g_Bhi + (size_t)n0 * rs + kb;
    const char* Bl = (const char*)g_Blo + (size_t)n0 * rs + kb;
    #pragma unroll
    for (int i = 0; i < 4; i++) {            // A: 1024 granules
        int idx = i * 256 + tid, row = idx >> 3, ch = idx & 7;
        const char* s = (ch < 4 ? Ah : Al) + (size_t)row * rs + (size_t)(ch & 3) * 16;
        cp16(st + row * 128 + ((ch ^ (row & 7)) << 4), s);
    }
    const uint32_t bs = st + A_BYTES;
    #pragma unroll
    for (int i = 0; i < 8; i++) {            // B: 2048 granules
        int idx = i * 256 + tid, row = idx >> 3, ch = idx & 7;
        const char* s = (ch < 4 ? Bh : Bl) + (size_t)row * rs + (size_t)(ch & 3) * 16;
        cp16(bs + row * 128 + ((ch ^ (row & 7)) << 4), s);
    }
}

__global__ void __launch_bounds__(256, 1) gemm_kernel(float* __restrict__ out) {
    extern __shared__ char smem_raw[];
    const uint32_t sb = (smem_u32(smem_raw) + 1023u) & ~1023u;
    const int tid = threadIdx.x, lane = tid & 31, w = tid >> 5;
    const int wm = w & 1, wn = w >> 1;       // 2 x 4 warp grid, warp tile 64x64
    const int m0 = blockIdx.y * BM, n0 = blockIdx.x * BN;

    // preload 3 stages
    #pragma unroll
    for (int s = 0; s < 3; s++) {
        load_stage(sb + s * STAGE_BYTES, s, m0, n0, tid);
        asm volatile("cp.async.commit_group;" ::: "memory");
    }

    float acc[4][8][4] = {};                 // 128 regs

    // ldmatrix per-lane row constants
    int aRow[4], bRow[4];
    #pragma unroll
    for (int mi = 0; mi < 4; mi++) aRow[mi] = wm * 64 + mi * 16 + (lane & 15);
    #pragma unroll
    for (int f = 0; f < 4; f++)
        bRow[f] = wn * 64 + f * 16 + ((lane >> 4) << 3) + (lane & 7);
    const int aSel = lane >> 4;              // k8 selector for A
    const int bSel = (lane >> 3) & 1;        // k8 selector for B

    for (int c = 0; c < NCH; c++) {
        asm volatile("cp.async.wait_group 2;" ::: "memory");
        __syncthreads();
        if (c + 3 < NCH) load_stage(sb + ((c + 3) & 3) * STAGE_BYTES, c + 3, m0, n0, tid);
        asm volatile("cp.async.commit_group;" ::: "memory");  // may be empty (tail)

        const uint32_t st = sb + (c & 3) * STAGE_BYTES;
        const uint32_t aB = st, bB = st + A_BYTES;

        #pragma unroll
        for (int q = 0; q < 2; q++) {        // two k16 halves of the chunk
            uint32_t ah[16], al[16], bb[8];
            #pragma unroll
            for (int mi = 0; mi < 4; mi++) {
                ldsm4(&ah[4 * mi], aB + aRow[mi] * 128 +
                      (((q * 2 + aSel) ^ (aRow[mi] & 7)) << 4));
                ldsm4(&al[4 * mi], aB + aRow[mi] * 128 +
                      (((4 + q * 2 + aSel) ^ (aRow[mi] & 7)) << 4));
            }
            // stream B in two 32-column halves through an 8-reg buffer
            #pragma unroll
            for (int h = 0; h < 2; h++) {
                #pragma unroll
                for (int g = 0; g < 2; g++) {        // Bhi
                    const int f = 2 * h + g;
                    ldsm4(&bb[4 * g], bB + bRow[f] * 128 +
                          (((q * 2 + bSel) ^ (bRow[f] & 7)) << 4));
                }
                #pragma unroll
                for (int mi = 0; mi < 4; mi++)
                    #pragma unroll
                    for (int j = 0; j < 4; j++)
                        mma_bf16(acc[mi][4 * h + j], &ah[4 * mi], &bb[2 * j]);  // hi*hi
                #pragma unroll
                for (int mi = 0; mi < 4; mi++)
                    #pragma unroll
                    for (int j = 0; j < 4; j++)
                        mma_bf16(acc[mi][4 * h + j], &al[4 * mi], &bb[2 * j]);  // lo*hi
                #pragma unroll
                for (int g = 0; g < 2; g++) {        // Blo overwrites buffer
                    const int f = 2 * h + g;
                    ldsm4(&bb[4 * g], bB + bRow[f] * 128 +
                          (((4 + q * 2 + bSel) ^ (bRow[f] & 7)) << 4));
                }
                #pragma unroll
                for (int mi = 0; mi < 4; mi++)
                    #pragma unroll
                    for (int j = 0; j < 4; j++)
                        mma_bf16(acc[mi][4 * h + j], &ah[4 * mi], &bb[2 * j]);  // hi*lo
            }
        }
    }

    // epilogue: out[m][n] = fea / deg   (RN division, matching reference)
    const int cw = n0 + wn * 64 + (lane & 3) * 2;
    #pragma unroll
    for (int mi = 0; mi < 4; mi++) {
        const int r0 = m0 + wm * 64 + mi * 16 + (lane >> 2);
        const float d0 = g_deg[r0];
        const float d1 = g_deg[r0 + 8];
        float* p0 = out + (size_t)r0 * DCOLS;
        float* p1 = out + (size_t)(r0 + 8) * DCOLS;
        #pragma unroll
        for (int ni = 0; ni < 8; ni++) {
            float2 v0 = make_float2(__fdiv_rn(acc[mi][ni][0], d0),
                                    __fdiv_rn(acc[mi][ni][1], d0));
            float2 v1 = make_float2(__fdiv_rn(acc[mi][ni][2], d1),
                                    __fdiv_rn(acc[mi][ni][3], d1));
            *(float2*)(p0 + cw + ni * 8) = v0;
            *(float2*)(p1 + cw + ni * 8) = v1;
        }
    }
}

// ---------------- launch ----------------
extern "C" void kernel_launch(void* const* d_in, const int* in_sizes, int n_in,
                              void* d_out, int out_size) {
    const float* cur = (const float*)d_in[0];
    const float* inc = (const float*)d_in[1];
    if (n_in >= 2 && in_sizes[0] == NROWS * NROWS) {  // defensive input-order check
        inc = (const float*)d_in[0];
        cur = (const float*)d_in[1];
    }
    cudaFuncSetAttribute(gemm_kernel, cudaFuncAttributeMaxDynamicSharedMemorySize,
                         SMEM_TOTAL);

    prep_rows<<<NROWS, 256>>>(inc);
    prep_B<<<dim3(NROWS / 32, DCOLS / 32), dim3(32, 8)>>>(cur);
    gemm_kernel<<<dim3(DCOLS / BN, NROWS / BM), 256, SMEM_TOTAL>>>((float*)d_out);
}

// round 7
// speedup vs baseline: 1.0639x; 1.0021x over previous
#include <cuda_runtime.h>
#include <cuda_bf16.h>
#include <cstdint>

#define NROWS 8192
#define DCOLS 512

// ---------------- scratch (device globals: allocation-free) ----------------
__device__ __align__(256) __nv_bfloat16 g_Ahi[(size_t)NROWS * NROWS];   // 128 MB
__device__ __align__(256) __nv_bfloat16 g_Alo[(size_t)NROWS * NROWS];   // 128 MB
__device__ __align__(256) __nv_bfloat16 g_Bhi[(size_t)DCOLS * NROWS];   // 8 MB [n][k]
__device__ __align__(256) __nv_bfloat16 g_Blo[(size_t)DCOLS * NROWS];   // 8 MB
__device__ float g_deg[NROWS];

// ---------------- PTX helpers (compute_100-safe: no 'a' features) ----------
__device__ __forceinline__ uint32_t smem_u32(const void* p) {
    uint32_t a;
    asm("{ .reg .u64 t; cvta.to.shared.u64 t, %1; cvt.u32.u64 %0, t; }" : "=r"(a) : "l"(p));
    return a;
}
__device__ __forceinline__ void cp16(uint32_t dst, const void* src) {
    asm volatile("cp.async.cg.shared.global [%0], [%1], 16;" :: "r"(dst), "l"(src));
}
__device__ __forceinline__ void ldsm4(uint32_t* r, uint32_t addr) {
    asm volatile("ldmatrix.sync.aligned.m8n8.x4.shared.b16 {%0,%1,%2,%3}, [%4];"
                 : "=r"(r[0]), "=r"(r[1]), "=r"(r[2]), "=r"(r[3]) : "r"(addr));
}
__device__ __forceinline__ void mma_bf16(float* c, const uint32_t* a, const uint32_t* b) {
    asm("mma.sync.aligned.m16n8k16.row.col.f32.bf16.bf16.f32 "
        "{%0,%1,%2,%3}, {%4,%5,%6,%7}, {%8,%9}, {%0,%1,%2,%3};"
        : "+f"(c[0]), "+f"(c[1]), "+f"(c[2]), "+f"(c[3])
        : "r"(a[0]), "r"(a[1]), "r"(a[2]), "r"(a[3]), "r"(b[0]), "r"(b[1]));
}
__device__ __forceinline__ uint32_t pack_bf16(float a, float b) {
    __nv_bfloat162 h = __halves2bfloat162(__float2bfloat16(a), __float2bfloat16(b));
    return *(uint32_t*)&h;
}

// ---------------- P1: row stats + A split + XLA-order deg ----------------
__global__ void __launch_bounds__(256) prep_rows(const float* __restrict__ inc) {
    __shared__ float row[NROWS];          // 32 KB
    __shared__ int   red_c[8];
    __shared__ float wpart[32];
    __shared__ float s_hv;

    const int r = blockIdx.x;
    const int tid = threadIdx.x;
    const int lane = tid & 31, warp = tid >> 5;

    const float4* src = (const float4*)(inc + (size_t)r * NROWS);
    float4* dst = (float4*)row;
    int cnt = 0;
    for (int i = tid; i < NROWS / 4; i += 256) {
        float4 v = src[i];
        dst[i] = v;
        cnt += (v.x > 0.f) + (v.y > 0.f) + (v.z > 0.f) + (v.w > 0.f);
    }
    for (int o = 16; o; o >>= 1) cnt += __shfl_xor_sync(0xFFFFFFFFu, cnt, o);
    if (lane == 0) red_c[warp] = cnt;
    __syncthreads();
    if (tid == 0) {
        int c = 0;
        #pragma unroll
        for (int i = 0; i < 8; i++) c += red_c[i];
        float denom = __fsqrt_rn((float)c);
        denom = fmaxf(denom, 1e-12f);
        s_hv = __fdiv_rn(1.0f, denom);
    }
    __syncthreads();
    const float hv = s_hv;

    // deg: XLA-GPU row-reduce order mimic (1024 virtual threads on 256 real)
    float accx[4], accy[4];
    #pragma unroll
    for (int jv = 0; jv < 4; jv++) { accx[jv] = 0.f; accy[jv] = 0.f; }
    #pragma unroll
    for (int jv = 0; jv < 4; jv++) {
        const int vt = tid + 256 * jv;
        #pragma unroll
        for (int i = 0; i < 4; i++) {
            const int j = 2 * vt + 2048 * i;
            float x = row[j];
            float y = row[j + 1];
            if (x > 0.f) x = x + hv;
            if (y > 0.f) y = y + hv;
            accx[jv] += x;
            accy[jv] += y;
        }
    }
    #pragma unroll
    for (int jv = 0; jv < 4; jv++) {
        float s = accx[jv] + accy[jv];
        s += __shfl_down_sync(0xFFFFFFFFu, s, 16);
        s += __shfl_down_sync(0xFFFFFFFFu, s, 8);
        s += __shfl_down_sync(0xFFFFFFFFu, s, 4);
        s += __shfl_down_sync(0xFFFFFFFFu, s, 2);
        s += __shfl_down_sync(0xFFFFFFFFu, s, 1);
        if (lane == 0) wpart[jv * 8 + warp] = s;
    }
    __syncthreads();
    if (tid < 32) {
        float v = wpart[tid];
        v += __shfl_down_sync(0xFFFFFFFFu, v, 16);
        v += __shfl_down_sync(0xFFFFFFFFu, v, 8);
        v += __shfl_down_sync(0xFFFFFFFFu, v, 4);
        v += __shfl_down_sync(0xFFFFFFFFu, v, 2);
        v += __shfl_down_sync(0xFFFFFFFFu, v, 1);
        if (tid == 0) g_deg[r] = v;
    }

    // bf16 hi/lo planes from a' (16-byte vectorized stores)
    uint4* hi = (uint4*)(g_Ahi + (size_t)r * NROWS);
    uint4* lo = (uint4*)(g_Alo + (size_t)r * NROWS);
    for (int i = tid; i < NROWS / 8; i += 256) {
        float a[8];
        #pragma unroll
        for (int e = 0; e < 8; e++) {
            float v = row[8 * i + e];
            if (v > 0.f) v = v + hv;
            a[e] = v;
        }
        uint4 h, l;
        h.x = pack_bf16(a[0], a[1]); h.y = pack_bf16(a[2], a[3]);
        h.z = pack_bf16(a[4], a[5]); h.w = pack_bf16(a[6], a[7]);
        float rl[8];
        #pragma unroll
        for (int e = 0; e < 8; e++) {
            __nv_bfloat16 hb = __float2bfloat16(a[e]);
            rl[e] = a[e] - __bfloat162float(hb);
        }
        l.x = pack_bf16(rl[0], rl[1]); l.y = pack_bf16(rl[2], rl[3]);
        l.z = pack_bf16(rl[4], rl[5]); l.w = pack_bf16(rl[6], rl[7]);
        hi[i] = h;
        lo[i] = l;
    }
}

// ---------------- P2: cur [k][n] -> B planes [n][k] (transpose + split) ------
__global__ void __launch_bounds__(256) prep_B(const float* __restrict__ cur) {
    __shared__ float t[32][33];
    const int k0 = blockIdx.x * 32;
    const int n0 = blockIdx.y * 32;
    const int tx = threadIdx.x, ty = threadIdx.y;
    for (int i = ty; i < 32; i += 8)
        t[i][tx] = cur[(size_t)(k0 + i) * DCOLS + n0 + tx];
    __syncthreads();
    for (int i = ty; i < 32; i += 8) {
        float v = t[tx][i];                  // cur[k0+tx][n0+i]
        size_t o = (size_t)(n0 + i) * NROWS + (size_t)(k0 + tx);
        __nv_bfloat16 h = __float2bfloat16(v);
        g_Bhi[o] = h;
        g_Blo[o] = __float2bfloat16(v - __bfloat162float(h));
    }
}

// ---------------- P3: mma.sync bf16x3 GEMM -----------------------------------
// CTA tile 128x128, 256 threads, warp grid 4(m) x 2(n), warp tile 32x64.
// 2 CTAs / SM (96 KB smem each) so barrier stalls overlap across CTAs.
constexpr int BM = 128, BN = 128, BK = 32, STAGES = 3;
constexpr int NCH = NROWS / BK;                 // 256 k-chunks
constexpr int A_BYTES = BM * 128;               // 16 KB  (row: hi 64B | lo 64B)
constexpr int B_BYTES = BN * 128;               // 16 KB
constexpr int STAGE_BYTES = A_BYTES + B_BYTES;  // 32 KB
constexpr int SMEM_TOTAL = 1024 + STAGES * STAGE_BYTES;  // 99328

__device__ __forceinline__ void load_stage(uint32_t st, int c, int m0, int n0, int tid) {
    const size_t rs = (size_t)NROWS * 2;     // 16384 B row stride
    const size_t kb = (size_t)c * 64;        // 32 bf16 = 64 B along k
    const char* Ah = (const char*)g_Ahi + (size_t)m0 * rs + kb;
    const char* Al = (const char*)g_Alo + (size_t)m0 * rs + kb;
    const char* Bh = (const char*)g_Bhi + (size_t)n0 * rs + kb;
    const char* Bl = (const char*)g_Blo + (size_t)n0 * rs + kb;
    #pragma unroll
    for (int i = 0; i < 4; i++) {            // A: 1024 granules
        int idx = i * 256 + tid, row = idx >> 3, ch = idx & 7;
        const char* s = (ch < 4 ? Ah : Al) + (size_t)row * rs + (size_t)(ch & 3) * 16;
        cp16(st + row * 128 + ((ch ^ (row & 7)) << 4), s);
    }
    const uint32_t bs = st + A_BYTES;
    #pragma unroll
    for (int i = 0; i < 4; i++) {            // B: 1024 granules
        int idx = i * 256 + tid, row = idx >> 3, ch = idx & 7;
        const char* s = (ch < 4 ? Bh : Bl) + (size_t)row * rs + (size_t)(ch & 3) * 16;
        cp16(bs + row * 128 + ((ch ^ (row & 7)) << 4), s);
    }
}

__global__ void __launch_bounds__(256, 2) gemm_kernel(float* __restrict__ out) {
    extern __shared__ char smem_raw[];
    const uint32_t sb = (smem_u32(smem_raw) + 1023u) & ~1023u;
    const int tid = threadIdx.x, lane = tid & 31, w = tid >> 5;
    const int wm = w & 3, wn = w >> 2;       // 4 x 2 warp grid, warp tile 32x64
    const int m0 = blockIdx.y * BM, n0 = blockIdx.x * BN;

    // preload 2 stages
    #pragma unroll
    for (int s = 0; s < 2; s++) {
        load_stage(sb + s * STAGE_BYTES, s, m0, n0, tid);
        asm volatile("cp.async.commit_group;" ::: "memory");
    }

    float acc[2][8][4] = {};                 // 64 regs

    // ldmatrix per-lane row constants
    int aRow[2], bRow[4];
    #pragma unroll
    for (int mi = 0; mi < 2; mi++) aRow[mi] = wm * 32 + mi * 16 + (lane & 15);
    #pragma unroll
    for (int f = 0; f < 4; f++)
        bRow[f] = wn * 64 + f * 16 + ((lane >> 4) << 3) + (lane & 7);
    const int aSel = lane >> 4;              // k8 selector for A
    const int bSel = (lane >> 3) & 1;        // k8 selector for B

    for (int c = 0; c < NCH; c++) {
        asm volatile("cp.async.wait_group 1;" ::: "memory");
        __syncthreads();
        if (c + 2 < NCH) load_stage(sb + ((c + 2) % 3) * STAGE_BYTES, c + 2, m0, n0, tid);
        asm volatile("cp.async.commit_group;" ::: "memory");  // may be empty (tail)

        const uint32_t st = sb + (c % 3) * STAGE_BYTES;
        const uint32_t aB = st, bB = st + A_BYTES;

        #pragma unroll
        for (int q = 0; q < 2; q++) {        // two k16 halves of the chunk
            uint32_t ah[8], al[8], bb[8];
            #pragma unroll
            for (int mi = 0; mi < 2; mi++) {
                ldsm4(&ah[4 * mi], aB + aRow[mi] * 128 +
                      (((q * 2 + aSel) ^ (aRow[mi] & 7)) << 4));
                ldsm4(&al[4 * mi], aB + aRow[mi] * 128 +
                      (((4 + q * 2 + aSel) ^ (aRow[mi] & 7)) << 4));
            }
            // stream B in two 32-column halves through an 8-reg buffer
            #pragma unroll
            for (int h = 0; h < 2; h++) {
                #pragma unroll
                for (int g = 0; g < 2; g++) {        // Bhi
                    const int f = 2 * h + g;
                    ldsm4(&bb[4 * g], bB + bRow[f] * 128 +
                          (((q * 2 + bSel) ^ (bRow[f] & 7)) << 4));
                }
                #pragma unroll
                for (int mi = 0; mi < 2; mi++)
                    #pragma unroll
                    for (int j = 0; j < 4; j++)
                        mma_bf16(acc[mi][4 * h + j], &ah[4 * mi], &bb[2 * j]);  // hi*hi
                #pragma unroll
                for (int mi = 0; mi < 2; mi++)
                    #pragma unroll
                    for (int j = 0; j < 4; j++)
                        mma_bf16(acc[mi][4 * h + j], &al[4 * mi], &bb[2 * j]);  // lo*hi
                #pragma unroll
                for (int g = 0; g < 2; g++) {        // Blo overwrites buffer
                    const int f = 2 * h + g;
                    ldsm4(&bb[4 * g], bB + bRow[f] * 128 +
                          (((4 + q * 2 + bSel) ^ (bRow[f] & 7)) << 4));
                }
                #pragma unroll
                for (int mi = 0; mi < 2; mi++)
                    #pragma unroll
                    for (int j = 0; j < 4; j++)
                        mma_bf16(acc[mi][4 * h + j], &ah[4 * mi], &bb[2 * j]);  // hi*lo
            }
        }
    }

    // epilogue: out[m][n] = fea / deg   (RN division, matching reference)
    const int cw = n0 + wn * 64 + (lane & 3) * 2;
    #pragma unroll
    for (int mi = 0; mi < 2; mi++) {
        const int r0 = m0 + wm * 32 + mi * 16 + (lane >> 2);
        const float d0 = g_deg[r0];
        const float d1 = g_deg[r0 + 8];
        float* p0 = out + (size_t)r0 * DCOLS;
        float* p1 = out + (size_t)(r0 + 8) * DCOLS;
        #pragma unroll
        for (int ni = 0; ni < 8; ni++) {
            float2 v0 = make_float2(__fdiv_rn(acc[mi][ni][0], d0),
                                    __fdiv_rn(acc[mi][ni][1], d0));
            float2 v1 = make_float2(__fdiv_rn(acc[mi][ni][2], d1),
                                    __fdiv_rn(acc[mi][ni][3], d1));
            *(float2*)(p0 + cw + ni * 8) = v0;
            *(float2*)(p1 + cw + ni * 8) = v1;
        }
    }
}

// ---------------- launch ----------------
extern "C" void kernel_launch(void* const* d_in, const int* in_sizes, int n_in,
                              void* d_out, int out_size) {
    const float* cur = (const float*)d_in[0];
    const float* inc = (const float*)d_in[1];
    if (n_in >= 2 && in_sizes[0] == NROWS * NROWS) {  // defensive input-order check
        inc = (const float*)d_in[0];
        cur = (const float*)d_in[1];
    }
    cudaFuncSetAttribute(gemm_kernel, cudaFuncAttributeMaxDynamicSharedMemorySize,
                         SMEM_TOTAL);

    prep_rows<<<NROWS, 256>>>(inc);
    prep_B<<<dim3(NROWS / 32, DCOLS / 32), dim3(32, 8)>>>(cur);
    gemm_kernel<<<dim3(DCOLS / BN, NROWS / BM), 256, SMEM_TOTAL>>>((float*)d_out);
}

// round 8
// speedup vs baseline: 1.6402x; 1.5416x over previous
#include <cuda_runtime.h>
#include <cuda_bf16.h>
#include <cstdint>

#define NROWS 8192
#define DCOLS 512

// ---------------- scratch (device globals: allocation-free) ----------------
__device__ __align__(256) int8_t g_A1[(size_t)NROWS * NROWS];   // 64 MB
__device__ __align__(256) int8_t g_A2[(size_t)NROWS * NROWS];   // 64 MB
__device__ __align__(256) int8_t g_B1[(size_t)DCOLS * NROWS];   // 4 MB [n][k]
__device__ __align__(256) int8_t g_B2[(size_t)DCOLS * NROWS];   // 4 MB
__device__ float g_deg[NROWS];
__device__ float g_Sa[NROWS];
__device__ float g_Sb[DCOLS];

// ---------------- PTX helpers (compute_100-safe: no 'a' features) ----------
__device__ __forceinline__ uint32_t smem_u32(const void* p) {
    uint32_t a;
    asm("{ .reg .u64 t; cvta.to.shared.u64 t, %1; cvt.u32.u64 %0, t; }" : "=r"(a) : "l"(p));
    return a;
}
__device__ __forceinline__ void cp16(uint32_t dst, const void* src) {
    asm volatile("cp.async.cg.shared.global [%0], [%1], 16;" :: "r"(dst), "l"(src));
}
__device__ __forceinline__ void ldsm4(uint32_t* r, uint32_t addr) {
    asm volatile("ldmatrix.sync.aligned.m8n8.x4.shared.b16 {%0,%1,%2,%3}, [%4];"
                 : "=r"(r[0]), "=r"(r[1]), "=r"(r[2]), "=r"(r[3]) : "r"(addr));
}
// s8 MMA, k32: fragments are byte-identical to the b16 k16 fragments.
__device__ __forceinline__ void mma_s8(int* c, const uint32_t* a, const uint32_t* b) {
    asm("mma.sync.aligned.m16n8k32.row.col.s32.s8.s8.s32 "
        "{%0,%1,%2,%3}, {%4,%5,%6,%7}, {%8,%9}, {%0,%1,%2,%3};"
        : "+r"(c[0]), "+r"(c[1]), "+r"(c[2]), "+r"(c[3])
        : "r"(a[0]), "r"(a[1]), "r"(a[2]), "r"(a[3]), "r"(b[0]), "r"(b[1]));
}
__device__ __forceinline__ uint32_t pack4(int b0, int b1, int b2, int b3) {
    return (b0 & 0xFF) | ((b1 & 0xFF) << 8) | ((b2 & 0xFF) << 16) | ((b3 & 0xFF) << 24);
}

// ---------------- P1: row stats + XLA-order deg + int8 quant ----------------
__global__ void __launch_bounds__(256) prep_rows(const float* __restrict__ inc) {
    __shared__ float row[NROWS];          // 32 KB
    __shared__ int   red_c[8];
    __shared__ float wpart[32];
    __shared__ float s_hv, s_inv;

    const int r = blockIdx.x;
    const int tid = threadIdx.x;
    const int lane = tid & 31, warp = tid >> 5;

    const float4* src = (const float4*)(inc + (size_t)r * NROWS);
    float4* dst = (float4*)row;
    int cnt = 0;
    for (int i = tid; i < NROWS / 4; i += 256) {
        float4 v = src[i];
        dst[i] = v;
        cnt += (v.x > 0.f) + (v.y > 0.f) + (v.z > 0.f) + (v.w > 0.f);
    }
    for (int o = 16; o; o >>= 1) cnt += __shfl_xor_sync(0xFFFFFFFFu, cnt, o);
    if (lane == 0) red_c[warp] = cnt;
    __syncthreads();
    if (tid == 0) {
        int c = 0;
        #pragma unroll
        for (int i = 0; i < 8; i++) c += red_c[i];
        float denom = __fsqrt_rn((float)c);
        denom = fmaxf(denom, 1e-12f);
        s_hv = __fdiv_rn(1.0f, denom);
    }
    __syncthreads();
    const float hv = s_hv;

    // deg: XLA-GPU row-reduce order mimic (1024 virtual threads on 256 real)
    float accx[4], accy[4];
    #pragma unroll
    for (int jv = 0; jv < 4; jv++) { accx[jv] = 0.f; accy[jv] = 0.f; }
    #pragma unroll
    for (int jv = 0; jv < 4; jv++) {
        const int vt = tid + 256 * jv;
        #pragma unroll
        for (int i = 0; i < 4; i++) {
            const int j = 2 * vt + 2048 * i;
            float x = row[j];
            float y = row[j + 1];
            if (x > 0.f) x = x + hv;
            if (y > 0.f) y = y + hv;
            accx[jv] += x;
            accy[jv] += y;
        }
    }
    #pragma unroll
    for (int jv = 0; jv < 4; jv++) {
        float s = accx[jv] + accy[jv];
        s += __shfl_down_sync(0xFFFFFFFFu, s, 16);
        s += __shfl_down_sync(0xFFFFFFFFu, s, 8);
        s += __shfl_down_sync(0xFFFFFFFFu, s, 4);
        s += __shfl_down_sync(0xFFFFFFFFu, s, 2);
        s += __shfl_down_sync(0xFFFFFFFFu, s, 1);
        if (lane == 0) wpart[jv * 8 + warp] = s;
    }
    __syncthreads();
    if (tid < 32) {
        float v = wpart[tid];
        v += __shfl_down_sync(0xFFFFFFFFu, v, 16);
        v += __shfl_down_sync(0xFFFFFFFFu, v, 8);
        v += __shfl_down_sync(0xFFFFFFFFu, v, 4);
        v += __shfl_down_sync(0xFFFFFFFFu, v, 2);
        v += __shfl_down_sync(0xFFFFFFFFu, v, 1);
        if (tid == 0) g_deg[r] = v;
    }
    __syncthreads();

    // row max of |a'|
    float mx = 0.f;
    for (int i = tid; i < NROWS / 4; i += 256) {
        float4 v = dst[i];
        float a0 = (v.x > 0.f) ? v.x + hv : v.x;
        float a1 = (v.y > 0.f) ? v.y + hv : v.y;
        float a2 = (v.z > 0.f) ? v.z + hv : v.z;
        float a3 = (v.w > 0.f) ? v.w + hv : v.w;
        mx = fmaxf(mx, fmaxf(fmaxf(fabsf(a0), fabsf(a1)), fmaxf(fabsf(a2), fabsf(a3))));
    }
    for (int o = 16; o; o >>= 1) mx = fmaxf(mx, __shfl_xor_sync(0xFFFFFFFFu, mx, o));
    if (lane == 0) wpart[warp] = mx;
    __syncthreads();
    if (tid == 0) {
        float m = 1e-30f;
        #pragma unroll
        for (int i = 0; i < 8; i++) m = fmaxf(m, wpart[i]);
        g_Sa[r] = m / 127.f;
        s_inv = 127.f / m;
    }
    __syncthreads();
    const float inv = s_inv;

    // quantize to two int8 planes: a' = Sa*(q1 + q2/254)
    uint2* p1 = (uint2*)(g_A1 + (size_t)r * NROWS);
    uint2* p2 = (uint2*)(g_A2 + (size_t)r * NROWS);
    for (int i = tid; i < NROWS / 8; i += 256) {
        int q1[8], q2[8];
        #pragma unroll
        for (int e = 0; e < 8; e++) {
            float a = row[8 * i + e];
            if (a > 0.f) a = a + hv;
            float q = a * inv;
            int i1 = __float2int_rn(q);
            int i2 = __float2int_rn(254.f * (q - (float)i1));
            q1[e] = i1; q2[e] = i2;
        }
        uint2 u1, u2;
        u1.x = pack4(q1[0], q1[1], q1[2], q1[3]);
        u1.y = pack4(q1[4], q1[5], q1[6], q1[7]);
        u2.x = pack4(q2[0], q2[1], q2[2], q2[3]);
        u2.y = pack4(q2[4], q2[5], q2[6], q2[7]);
        p1[i] = u1;
        p2[i] = u2;
    }
}

// ---------------- P2a: per-column max of cur -> g_Sb ----------------
__global__ void __launch_bounds__(256) prep_Bscale(const float* __restrict__ cur) {
    __shared__ float red[32][8];
    const int tid = threadIdx.x;
    const int nIn = tid & 7;
    const int kp = tid >> 3;                  // 0..31
    const int n = blockIdx.x * 8 + nIn;
    float m = 0.f;
    for (int k = kp; k < NROWS; k += 32)
        m = fmaxf(m, fabsf(cur[(size_t)k * DCOLS + n]));
    red[kp][nIn] = m;
    __syncthreads();
    if (tid < 8) {
        float mm = 1e-30f;
        #pragma unroll
        for (int i = 0; i < 32; i++) mm = fmaxf(mm, red[i][tid]);
        g_Sb[blockIdx.x * 8 + tid] = mm / 127.f;
    }
}

// ---------------- P2b: cur [k][n] -> int8 planes [n][k] ----------------
__global__ void __launch_bounds__(256) prep_B(const float* __restrict__ cur) {
    __shared__ float t[32][33];
    const int k0 = blockIdx.x * 32;
    const int n0 = blockIdx.y * 32;
    const int tx = threadIdx.x, ty = threadIdx.y;
    for (int i = ty; i < 32; i += 8)
        t[i][tx] = cur[(size_t)(k0 + i) * DCOLS + n0 + tx];
    __syncthreads();
    for (int i = ty; i < 32; i += 8) {
        const int n = n0 + i;
        float v = t[tx][i];                  // cur[k0+tx][n]
        float q = v / g_Sb[n];
        int i1 = __float2int_rn(q);
        int i2 = __float2int_rn(254.f * (q - (float)i1));
        size_t o = (size_t)n * NROWS + (size_t)(k0 + tx);
        g_B1[o] = (int8_t)i1;
        g_B2[o] = (int8_t)i2;
    }
}

// ---------------- P3: int8 x3 GEMM ------------------------------------------
// CTA tile 128x128, BK=64, 256 threads, warp grid 4(m) x 2(n), warp tile 32x64.
constexpr int BM = 128, BN = 128, BK = 64, STAGES = 3;
constexpr int NCH = NROWS / BK;                 // 128 k-chunks
constexpr int A_BYTES = BM * 128;               // 16 KB (row: q1 64B | q2 64B)
constexpr int B_BYTES = BN * 128;               // 16 KB
constexpr int STAGE_BYTES = A_BYTES + B_BYTES;  // 32 KB
constexpr int SMEM_TOTAL = 1024 + STAGES * STAGE_BYTES;  // 99328

__device__ __forceinline__ void load_stage(uint32_t st, int c, int m0, int n0, int tid) {
    const size_t rs = (size_t)NROWS;         // 8192 B row stride (int8)
    const size_t kb = (size_t)c * 64;        // 64 int8 along k
    const char* A1 = (const char*)g_A1 + (size_t)m0 * rs + kb;
    const char* A2 = (const char*)g_A2 + (size_t)m0 * rs + kb;
    const char* B1 = (const char*)g_B1 + (size_t)n0 * rs + kb;
    const char* B2 = (const char*)g_B2 + (size_t)n0 * rs + kb;
    #pragma unroll
    for (int i = 0; i < 4; i++) {            // A: 1024 granules
        int idx = i * 256 + tid, row = idx >> 3, g = idx & 7;
        const char* s = (g < 4 ? A1 : A2) + (size_t)row * rs + (size_t)(g & 3) * 16;
        cp16(st + row * 128 + ((g ^ (row & 7)) << 4), s);
    }
    const uint32_t bs = st + A_BYTES;
    #pragma unroll
    for (int i = 0; i < 4; i++) {            // B: 1024 granules
        int idx = i * 256 + tid, row = idx >> 3, g = idx & 7;
        const char* s = (g < 4 ? B1 : B2) + (size_t)row * rs + (size_t)(g & 3) * 16;
        cp16(bs + row * 128 + ((g ^ (row & 7)) << 4), s);
    }
}

__global__ void __launch_bounds__(256, 1) gemm_kernel(float* __restrict__ out) {
    extern __shared__ char smem_raw[];
    const uint32_t sb = (smem_u32(smem_raw) + 1023u) & ~1023u;
    const int tid = threadIdx.x, lane = tid & 31, w = tid >> 5;
    const int wm = w & 3, wn = w >> 2;       // 4 x 2 warp grid, warp tile 32x64
    const int m0 = blockIdx.y * BM, n0 = blockIdx.x * BN;

    // preload 2 stages
    #pragma unroll
    for (int s = 0; s < 2; s++) {
        load_stage(sb + s * STAGE_BYTES, s, m0, n0, tid);
        asm volatile("cp.async.commit_group;" ::: "memory");
    }

    int am[2][8][4] = {};                    // main: a1*b1
    int ax[2][8][4] = {};                    // cross: a1*b2 + a2*b1

    int aRow[2], bRow[4];
    #pragma unroll
    for (int mi = 0; mi < 2; mi++) aRow[mi] = wm * 32 + mi * 16 + (lane & 15);
    #pragma unroll
    for (int f = 0; f < 4; f++)
        bRow[f] = wn * 64 + f * 16 + ((lane >> 4) << 3) + (lane & 7);
    const int aSel = lane >> 4;              // k32-half granule selector
    const int bSel = (lane >> 3) & 1;

    for (int c = 0; c < NCH; c++) {
        asm volatile("cp.async.wait_group 1;" ::: "memory");
        __syncthreads();
        if (c + 2 < NCH) load_stage(sb + ((c + 2) % 3) * STAGE_BYTES, c + 2, m0, n0, tid);
        asm volatile("cp.async.commit_group;" ::: "memory");  // may be empty (tail)

        const uint32_t st = sb + (c % 3) * STAGE_BYTES;
        const uint32_t aB = st, bB = st + A_BYTES;

        #pragma unroll
        for (int q = 0; q < 2; q++) {        // two k32 halves of the chunk
            uint32_t ah[8], al[8], bb[8];
            #pragma unroll
            for (int mi = 0; mi < 2; mi++) {
                ldsm4(&ah[4 * mi], aB + aRow[mi] * 128 +
                      (((q * 2 + aSel) ^ (aRow[mi] & 7)) << 4));     // plane q1
                ldsm4(&al[4 * mi], aB + aRow[mi] * 128 +
                      (((4 + q * 2 + aSel) ^ (aRow[mi] & 7)) << 4)); // plane q2
            }
            #pragma unroll
            for (int h = 0; h < 2; h++) {    // two 32-col halves of N
                #pragma unroll
                for (int g = 0; g < 2; g++) {        // B plane b1
                    const int f = 2 * h + g;
                    ldsm4(&bb[4 * g], bB + bRow[f] * 128 +
                          (((q * 2 + bSel) ^ (bRow[f] & 7)) << 4));
                }
                #pragma unroll
                for (int mi = 0; mi < 2; mi++)
                    #pragma unroll
                    for (int j = 0; j < 4; j++)
                        mma_s8(am[mi][4 * h + j], &ah[4 * mi], &bb[2 * j]);  // a1*b1
                #pragma unroll
                for (int mi = 0; mi < 2; mi++)
                    #pragma unroll
                    for (int j = 0; j < 4; j++)
                        mma_s8(ax[mi][4 * h + j], &al[4 * mi], &bb[2 * j]);  // a2*b1
                #pragma unroll
                for (int g = 0; g < 2; g++) {        // B plane b2 overwrites
                    const int f = 2 * h + g;
                    ldsm4(&bb[4 * g], bB + bRow[f] * 128 +
                          (((4 + q * 2 + bSel) ^ (bRow[f] & 7)) << 4));
                }
                #pragma unroll
                for (int mi = 0; mi < 2; mi++)
                    #pragma unroll
                    for (int j = 0; j < 4; j++)
                        mma_s8(ax[mi][4 * h + j], &ah[4 * mi], &bb[2 * j]);  // a1*b2
            }
        }
    }

    // epilogue: fea = Sa*Sb*(main + cross/254);  out = fea / deg (RN)
    const float C = 1.f / 254.f;
    const int cw = n0 + wn * 64 + (lane & 3) * 2;
    #pragma unroll
    for (int mi = 0; mi < 2; mi++) {
        const int r0 = m0 + wm * 32 + mi * 16 + (lane >> 2);
        const float d0 = g_deg[r0], d1 = g_deg[r0 + 8];
        const float sa0 = g_Sa[r0], sa1 = g_Sa[r0 + 8];
        float* p0 = out + (size_t)r0 * DCOLS;
        float* p1 = out + (size_t)(r0 + 8) * DCOLS;
        #pragma unroll
        for (int ni = 0; ni < 8; ni++) {
            const int col = cw + ni * 8;
            float2 sbv = *(const float2*)(g_Sb + col);
            float f00 = sa0 * sbv.x * ((float)am[mi][ni][0] + (float)ax[mi][ni][0] * C);
            float f01 = sa0 * sbv.y * ((float)am[mi][ni][1] + (float)ax[mi][ni][1] * C);
            float f10 = sa1 * sbv.x * ((float)am[mi][ni][2] + (float)ax[mi][ni][2] * C);
            float f11 = sa1 * sbv.y * ((float)am[mi][ni][3] + (float)ax[mi][ni][3] * C);
            float2 v0 = make_float2(__fdiv_rn(f00, d0), __fdiv_rn(f01, d0));
            float2 v1 = make_float2(__fdiv_rn(f10, d1), __fdiv_rn(f11, d1));
            *(float2*)(p0 + col) = v0;
            *(float2*)(p1 + col) = v1;
        }
    }
}

// ---------------- launch ----------------
extern "C" void kernel_launch(void* const* d_in, const int* in_sizes, int n_in,
                              void* d_out, int out_size) {
    const float* cur = (const float*)d_in[0];
    const float* inc = (const float*)d_in[1];
    if (n_in >= 2 && in_sizes[0] == NROWS * NROWS) {  // defensive input-order check
        inc = (const float*)d_in[0];
        cur = (const float*)d_in[1];
    }
    cudaFuncSetAttribute(gemm_kernel, cudaFuncAttributeMaxDynamicSharedMemorySize,
                         SMEM_TOTAL);

    prep_rows<<<NROWS, 256>>>(inc);
    prep_Bscale<<<DCOLS / 8, 256>>>(cur);
    prep_B<<<dim3(NROWS / 32, DCOLS / 32), dim3(32, 8)>>>(cur);
    gemm_kernel<<<dim3(DCOLS / BN, NROWS / BM), 256, SMEM_TOTAL>>>((float*)d_out);
}